// round 12
// baseline (speedup 1.0000x reference)
#include <cuda_runtime.h>
#include <cuda_bf16.h>
#include <math.h>
#include <float.h>

#define NB 16
#define NT 128
#define NK 1024
#define ND 768
#define NKP 102
#define NBT (NB*NT)
#define INV_SQRT_D 0.03608439182435161f
#define NEG_INF (-3.402823466e38f)

// ---------------- device scratch (no allocations allowed) ----------------
__device__ __align__(16) static float g_emission[NBT * NK];     // 8 MB
__device__ __align__(16) static float g_transition[NK * NK];    // 4 MB (symmetric)
__device__ __align__(16) static float g_alpha_sum[2][NB * NK];
__device__ __align__(16) static float g_alpha_vit[2][NB * NK];
__device__ static unsigned short g_bp[(NT - 1) * NB * NK];      // backpointers
__device__ __align__(16) static float g_emtop[NBT * NKP];
__device__ __align__(16) static int   g_topidx[NBT * NKP];
__device__ __align__(16) static float g_appx[2][NB * NKP];
__device__ static float g_rowlse[NBT];
__device__ static float g_maxprob[NBT];
__device__ static float g_emy[NBT];
__device__ static int   g_smpred[NBT];
__device__ static float g_logZ[NB];
__device__ static float g_logZa[NB];
__device__ static int   g_crf[NBT];

// ---------------- GEMM: C[M,N] = scale * A[.,768] * B[.,768]^T ----------------
__device__ __forceinline__ void gemm_body(const float* __restrict__ A,
                                          const float* __restrict__ B,
                                          float* __restrict__ C,
                                          int N, float scale)
{
    __shared__ __align__(16) float As[16][64];
    __shared__ __align__(16) float Bs[16][64];
    int tid = threadIdx.x;
    int tx = tid & 15, ty = tid >> 4;
    int m0 = blockIdx.y * 64, n0 = blockIdx.x * 64;
    int lr = tid >> 2;            // 0..63
    int lc = (tid & 3) << 2;      // 0,4,8,12
    float acc[4][4];
#pragma unroll
    for (int i = 0; i < 4; i++)
#pragma unroll
        for (int j = 0; j < 4; j++) acc[i][j] = 0.f;

    for (int d0 = 0; d0 < ND; d0 += 16) {
        float4 a4 = *(const float4*)(A + (size_t)(m0 + lr) * ND + d0 + lc);
        float4 b4 = *(const float4*)(B + (size_t)(n0 + lr) * ND + d0 + lc);
        As[lc + 0][lr] = a4.x; As[lc + 1][lr] = a4.y; As[lc + 2][lr] = a4.z; As[lc + 3][lr] = a4.w;
        Bs[lc + 0][lr] = b4.x; Bs[lc + 1][lr] = b4.y; Bs[lc + 2][lr] = b4.z; Bs[lc + 3][lr] = b4.w;
        __syncthreads();
#pragma unroll
        for (int kk = 0; kk < 16; kk++) {
            float4 av = *(const float4*)(&As[kk][ty * 4]);
            float4 bv = *(const float4*)(&Bs[kk][tx * 4]);
            acc[0][0] += av.x * bv.x; acc[0][1] += av.x * bv.y; acc[0][2] += av.x * bv.z; acc[0][3] += av.x * bv.w;
            acc[1][0] += av.y * bv.x; acc[1][1] += av.y * bv.y; acc[1][2] += av.y * bv.z; acc[1][3] += av.y * bv.w;
            acc[2][0] += av.z * bv.x; acc[2][1] += av.z * bv.y; acc[2][2] += av.z * bv.z; acc[2][3] += av.z * bv.w;
            acc[3][0] += av.w * bv.x; acc[3][1] += av.w * bv.y; acc[3][2] += av.w * bv.z; acc[3][3] += av.w * bv.w;
        }
        __syncthreads();
    }
#pragma unroll
    for (int i = 0; i < 4; i++) {
        float4 o;
        o.x = acc[i][0] * scale; o.y = acc[i][1] * scale;
        o.z = acc[i][2] * scale; o.w = acc[i][3] * scale;
        *(float4*)(C + (size_t)(m0 + ty * 4 + i) * N + n0 + tx * 4) = o;
    }
}

__global__ __launch_bounds__(256) void k_gemm_em(const float* __restrict__ x,
                                                 const float* __restrict__ S)
{ gemm_body(x, S, g_emission, NK, INV_SQRT_D); }

__global__ __launch_bounds__(256) void k_gemm_tr(const float* __restrict__ S)
{ gemm_body(S, S, g_transition, NK, INV_SQRT_D); }

// ---------------- top-k (bitonic sort; slot order is irrelevant downstream) ----------------
__global__ __launch_bounds__(512) void topk_kernel(const int* __restrict__ y_lens)
{
    int row = blockIdx.x;
    int b = row >> 7, t = row & 127;
    if (t >= y_lens[b]) return;
    __shared__ float sv[NK];
    __shared__ int   si[NK];
    int tid = threadIdx.x;
    const float* em = g_emission + (size_t)row * NK;
    sv[tid] = em[tid];             si[tid] = tid;
    sv[tid + 512] = em[tid + 512]; si[tid + 512] = tid + 512;
    __syncthreads();
    for (int k = 2; k <= NK; k <<= 1) {
        for (int j = k >> 1; j > 0; j >>= 1) {
#pragma unroll 1
            for (int base = 0; base < NK; base += 512) {
                int i = base + tid;
                int ixj = i ^ j;
                if (ixj > i) {
                    bool up = ((i & k) == 0);
                    float a = sv[i], c = sv[ixj];
                    if ((a > c) == up) {
                        sv[i] = c; sv[ixj] = a;
                        int tmp = si[i]; si[i] = si[ixj]; si[ixj] = tmp;
                    }
                }
            }
            __syncthreads();
        }
    }
    if (tid < NKP) {
        g_emtop[(size_t)row * NKP + tid]  = sv[NK - NKP + tid];
        g_topidx[(size_t)row * NKP + tid] = si[NK - NKP + tid];
    }
}

// ---------------- per-row: lse, argmax(first-idx), max softmax prob, em_y ----------------
__global__ __launch_bounds__(256) void rowstats_kernel(const int* __restrict__ y)
{
    int row = blockIdx.x * 8 + (threadIdx.x >> 5);
    int lane = threadIdx.x & 31;
    const float* em = g_emission + (size_t)row * NK;
    float m = NEG_INF; int mi = 0;
    for (int i = lane; i < NK; i += 32) {
        float v = em[i];
        if (v > m) { m = v; mi = i; }
    }
#pragma unroll
    for (int off = 16; off; off >>= 1) {
        float om = __shfl_xor_sync(0xffffffffu, m, off);
        int   oi = __shfl_xor_sync(0xffffffffu, mi, off);
        if (om > m || (om == m && oi < mi)) { m = om; mi = oi; }
    }
    float s = 0.f;
    for (int i = lane; i < NK; i += 32) s += expf(em[i] - m);
#pragma unroll
    for (int off = 16; off; off >>= 1) s += __shfl_xor_sync(0xffffffffu, s, off);
    if (lane == 0) {
        float lse = m + logf(s);
        g_rowlse[row]  = lse;
        g_smpred[row]  = mi;
        g_maxprob[row] = expf(m - lse);
        g_emy[row]     = em[y[row]];
    }
}

// ---------------- init alphas at t=0 ----------------
__global__ __launch_bounds__(1024) void init_kernel()
{
    int b = blockIdx.x, tid = threadIdx.x;
    float e = g_emission[(size_t)(b << 7) * NK + tid];
    g_alpha_sum[0][(b << 10) + tid] = e;
    g_alpha_vit[0][(b << 10) + tid] = e;
    if (tid < NKP)
        g_appx[0][b * NKP + tid] = g_emtop[(size_t)(b << 7) * NKP + tid];
}

// ---------------- one step: exact forward + viterbi + approx forward ----------------
__global__ __launch_bounds__(256) void step_kernel(int t, const int* __restrict__ y_lens)
{
    int blk = blockIdx.x;
    int tid = threadIdx.x;
    if (blk < 128) {
        int b = blk >> 3, part = blk & 7;
        int len = y_lens[b];
        if (t >= len) return;
        const float* __restrict__ prevS = g_alpha_sum[(t - 1) & 1] + (b << 10);
        const float* __restrict__ prevV = g_alpha_vit[(t - 1) & 1] + (b << 10);
        float* __restrict__ curS = g_alpha_sum[t & 1] + (b << 10);
        float* __restrict__ curV = g_alpha_vit[t & 1] + (b << 10);
        __shared__ __align__(16) float shS[NK];
        __shared__ __align__(16) float shV[NK];
        float shift = prevS[0];
        for (int i = tid; i < NK; i += 256) {
            shS[i] = prevS[i] - shift;
            shV[i] = prevV[i];
        }
        __syncthreads();
        int w = tid >> 5, lane = tid & 31;
        int jbase = part * 128 + w * 16;
        float acc[16], vmax[16];
        int vidx[16];
#pragma unroll
        for (int jj = 0; jj < 16; jj++) { acc[jj] = 0.f; vmax[jj] = NEG_INF; vidx[jj] = 0; }
#pragma unroll 1
        for (int i0 = 0; i0 < NK; i0 += 128) {
            int i = i0 + (lane << 2);
            float4 as4 = *(const float4*)(shS + i);
            float4 av4 = *(const float4*)(shV + i);
#pragma unroll
            for (int jj = 0; jj < 16; jj++) {
                // T is symmetric bitwise: read row (jbase+jj) contiguous in i
                float4 t4 = __ldg((const float4*)(g_transition + (size_t)(jbase + jj) * NK + i));
                acc[jj] += __expf(as4.x + t4.x) + __expf(as4.y + t4.y)
                         + __expf(as4.z + t4.z) + __expf(as4.w + t4.w);
                float v0 = av4.x + t4.x; if (v0 > vmax[jj]) { vmax[jj] = v0; vidx[jj] = i; }
                float v1 = av4.y + t4.y; if (v1 > vmax[jj]) { vmax[jj] = v1; vidx[jj] = i + 1; }
                float v2 = av4.z + t4.z; if (v2 > vmax[jj]) { vmax[jj] = v2; vidx[jj] = i + 2; }
                float v3 = av4.w + t4.w; if (v3 > vmax[jj]) { vmax[jj] = v3; vidx[jj] = i + 3; }
            }
        }
        const float* emrow = g_emission + (size_t)((b << 7) + t) * NK;
#pragma unroll
        for (int jj = 0; jj < 16; jj++) {
            float a = acc[jj], m = vmax[jj];
            int id = vidx[jj];
#pragma unroll
            for (int off = 16; off; off >>= 1) {
                a += __shfl_xor_sync(0xffffffffu, a, off);
                float om = __shfl_xor_sync(0xffffffffu, m, off);
                int   oi = __shfl_xor_sync(0xffffffffu, id, off);
                if (om > m || (om == m && oi < id)) { m = om; id = oi; }
            }
            if (lane == 0) {
                int j = jbase + jj;
                float em = emrow[j];
                curS[j] = shift + __logf(a) + em;
                curV[j] = m + em;
                g_bp[(size_t)(t - 1) * (NB * NK) + (b << 10) + j] = (unsigned short)id;
            }
        }
    } else {
        // approx forward step for batch b
        int b = blk - 128;
        int len = y_lens[b];
        if (t >= len) return;
        int row = (b << 7) + t, prow = row - 1;
        __shared__ float pA[NKP];
        __shared__ int   pI[NKP];
        if (tid < NKP) {
            pA[tid] = g_appx[(t - 1) & 1][b * NKP + tid];
            pI[tid] = g_topidx[(size_t)prow * NKP + tid];
        }
        __syncthreads();
        if (tid < NKP) {
            float shift = pA[0];
            int jc = g_topidx[(size_t)row * NKP + tid];
            float s = 0.f;
#pragma unroll 1
            for (int i = 0; i < NKP; i++)
                s += __expf(pA[i] - shift + __ldg(g_transition + (size_t)pI[i] * NK + jc));
            g_appx[t & 1][b * NKP + tid] =
                shift + __logf(s) + g_emtop[(size_t)row * NKP + tid];
        }
    }
}

// ---------------- last-state / log_Z / backtrace ----------------
__global__ __launch_bounds__(512) void trace_kernel(const int* __restrict__ y_lens,
                                                    float* __restrict__ out)
{
    __shared__ int sh_last[NB];
    int tid = threadIdx.x;
    int b = tid >> 5, lane = tid & 31;
    int len = y_lens[b];
    int par = (len - 1) & 1;
    {   // argmax of viterbi a_last (first index on ties)
        const float* av = g_alpha_vit[par] + (b << 10);
        float m = NEG_INF; int mi = 0;
        for (int j = lane; j < NK; j += 32) {
            float v = av[j];
            if (v > m) { m = v; mi = j; }
        }
#pragma unroll
        for (int off = 16; off; off >>= 1) {
            float om = __shfl_xor_sync(0xffffffffu, m, off);
            int   oi = __shfl_xor_sync(0xffffffffu, mi, off);
            if (om > m || (om == m && oi < mi)) { m = om; mi = oi; }
        }
        if (lane == 0) sh_last[b] = mi;
    }
    {   // log_Z (exact)
        const float* as = g_alpha_sum[par] + (b << 10);
        float m = NEG_INF;
        for (int j = lane; j < NK; j += 32) m = fmaxf(m, as[j]);
#pragma unroll
        for (int off = 16; off; off >>= 1) m = fmaxf(m, __shfl_xor_sync(0xffffffffu, m, off));
        float s = 0.f;
        for (int j = lane; j < NK; j += 32) s += expf(as[j] - m);
#pragma unroll
        for (int off = 16; off; off >>= 1) s += __shfl_xor_sync(0xffffffffu, s, off);
        if (lane == 0) g_logZ[b] = m + logf(s);
    }
    {   // log_Z approx
        const float* aa = g_appx[par] + b * NKP;
        float m = NEG_INF;
        for (int j = lane; j < NKP; j += 32) m = fmaxf(m, aa[j]);
#pragma unroll
        for (int off = 16; off; off >>= 1) m = fmaxf(m, __shfl_xor_sync(0xffffffffu, m, off));
        float s = 0.f;
        for (int j = lane; j < NKP; j += 32) s += expf(aa[j] - m);
#pragma unroll
        for (int off = 16; off; off >>= 1) s += __shfl_xor_sync(0xffffffffu, s, off);
        if (lane == 0) g_logZa[b] = m + logf(s);
    }
    __syncthreads();
    if (tid < NB) {
        int bb = tid;
        int ll = y_lens[bb];
        int last = sh_last[bb];
        int s = 0;
        for (int t = NT - 1; t >= 0; --t) {
            if (t == ll - 1)      s = last;
            else if (t < ll - 1)  s = (int)g_bp[(size_t)t * (NB * NK) + (bb << 10) + s];
            else                  s = 0;
            g_crf[(bb << 7) + t] = s;
            out[1 + (bb << 7) + t] = (float)s;
        }
    }
}

// ---------------- final scalar reductions ----------------
__global__ __launch_bounds__(512) void final_kernel(const int* __restrict__ y,
                                                    const int* __restrict__ y_lens,
                                                    float* __restrict__ out)
{
    __shared__ float sh_emy[NB], sh_lse[NB], sh_tr[NB], sh_mp[NB];
    __shared__ float sh_sup[NB], sh_eqc[NB], sh_pc[NB], sh_ovc[NB];
    __shared__ float sh_eqs[NB], sh_ps[NB], sh_ovs[NB];
    int tid = threadIdx.x;
    int b = tid >> 5, lane = tid & 31;
    int len = y_lens[b];
    float emy = 0.f, lse = 0.f, tr = 0.f, mp = 0.f;
    float sup = 0.f, eqc = 0.f, pc = 0.f, ovc = 0.f, eqs = 0.f, ps = 0.f, ovs = 0.f;
    for (int t = lane; t < NT; t += 32) {
        int row = (b << 7) + t;
        if (t < len) {
            emy += g_emy[row];
            lse += g_rowlse[row];
            mp  += g_maxprob[row];
            int yv = y[row];
            int cp = g_crf[row];
            int sp = g_smpred[row];
            sup += (yv > 0) ? 1.f : 0.f;
            eqc += (cp == yv) ? 1.f : 0.f;
            pc  += (cp > 0) ? 1.f : 0.f;
            ovc += (cp > 0 && yv > 0) ? 1.f : 0.f;
            eqs += (sp == yv) ? 1.f : 0.f;
            ps  += (sp > 0) ? 1.f : 0.f;
            ovs += (sp > 0 && yv > 0) ? 1.f : 0.f;
        }
        if (t < NT - 1 && t < len - 1)
            tr += g_transition[(size_t)y[(b << 7) + t] * NK + y[(b << 7) + t + 1]];
    }
#pragma unroll
    for (int off = 16; off; off >>= 1) {
        emy += __shfl_xor_sync(0xffffffffu, emy, off);
        lse += __shfl_xor_sync(0xffffffffu, lse, off);
        tr  += __shfl_xor_sync(0xffffffffu, tr,  off);
        mp  += __shfl_xor_sync(0xffffffffu, mp,  off);
        sup += __shfl_xor_sync(0xffffffffu, sup, off);
        eqc += __shfl_xor_sync(0xffffffffu, eqc, off);
        pc  += __shfl_xor_sync(0xffffffffu, pc,  off);
        ovc += __shfl_xor_sync(0xffffffffu, ovc, off);
        eqs += __shfl_xor_sync(0xffffffffu, eqs, off);
        ps  += __shfl_xor_sync(0xffffffffu, ps,  off);
        ovs += __shfl_xor_sync(0xffffffffu, ovs, off);
    }
    if (lane == 0) {
        sh_emy[b] = emy; sh_lse[b] = lse; sh_tr[b] = tr; sh_mp[b] = mp;
        sh_sup[b] = sup; sh_eqc[b] = eqc; sh_pc[b] = pc; sh_ovc[b] = ovc;
        sh_eqs[b] = eqs; sh_ps[b] = ps; sh_ovs[b] = ovs;
    }
    __syncthreads();
    if (tid == 0) {
        float totlen = 0.f;
        float sZ = 0.f, sZa = 0.f, sExact = 0.f, sApprox = 0.f, sLocal = 0.f, sMp = 0.f;
        float tsup = 0.f, teqc = 0.f, tpc = 0.f, tovc = 0.f, teqs = 0.f, tps = 0.f, tovs = 0.f;
        for (int bb = 0; bb < NB; bb++) {
            totlen += (float)y_lens[bb];
            float logpot = sh_emy[bb] + sh_tr[bb];
            sZ  += g_logZ[bb];
            sZa += g_logZa[bb];
            sExact  += logpot - g_logZ[bb];
            sApprox += logpot - g_logZa[bb];
            sLocal  += sh_emy[bb] - sh_lse[bb];
            sMp     += sh_mp[bb];
            tsup += sh_sup[bb]; teqc += sh_eqc[bb]; tpc += sh_pc[bb]; tovc += sh_ovc[bb];
            teqs += sh_eqs[bb]; tps += sh_ps[bb]; tovs += sh_ovs[bb];
        }
        float exactv  = -sExact / (float)NB;
        float approxv = -sApprox / (float)NB;
        float localv  = sLocal / totlen;
        float maxpv   = sMp / totlen;
        float loss    = approxv + 0.1f * localv;

        float crf_acc = teqc / totlen;
        float crf_prec = (tpc > 0.f) ? tovc / fmaxf(tpc, 1.f) : 0.f;
        float crf_recl = tovc / fmaxf(tsup, 1.f);
        float crf_f1 = (crf_prec > 0.f)
            ? 2.f * crf_prec * crf_recl / fmaxf(crf_prec + crf_recl, 1e-12f) : 0.f;

        float sm_acc = teqs / totlen;
        float sm_prec = (tps > 0.f) ? tovs / fmaxf(tps, 1.f) : 0.f;
        float sm_recl = tovs / fmaxf(tsup, 1.f);
        float sm_f1 = (sm_prec > 0.f)
            ? 2.f * sm_prec * sm_recl / fmaxf(sm_prec + sm_recl, 1e-12f) : 0.f;

        out[0]    = loss;
        out[2049] = sZ / (float)NB;
        out[2050] = sZa / (float)NB;
        out[2051] = exactv;
        out[2052] = localv;
        out[2053] = maxpv;
        out[2054] = crf_acc;
        out[2055] = crf_f1;
        out[2056] = sm_acc;
        out[2057] = sm_f1;
    }
}

// ---------------- launch ----------------
extern "C" void kernel_launch(void* const* d_in, const int* in_sizes, int n_in,
                              void* d_out, int out_size) {
    const float* x_emb = (const float*)d_in[0];
    const float* S     = (const float*)d_in[1];
    const int*   y     = (const int*)d_in[2];
    const int*   lens  = (const int*)d_in[3];
    float* out = (float*)d_out;

    k_gemm_tr<<<dim3(16, 16), 256>>>(S);
    k_gemm_em<<<dim3(16, 32), 256>>>(x_emb, S);
    topk_kernel<<<NBT, 512>>>(lens);
    rowstats_kernel<<<256, 256>>>(y);
    init_kernel<<<NB, 1024>>>();
    for (int t = 1; t < NT; t++)
        step_kernel<<<144, 256>>>(t, lens);
    trace_kernel<<<1, 512>>>(lens, out);
    final_kernel<<<1, 512>>>(y, lens, out);
}

// round 13
// speedup vs baseline: 2.5596x; 2.5596x over previous
#include <cuda_runtime.h>
#include <cuda_bf16.h>
#include <math.h>
#include <float.h>

#define NB 16
#define NT 128
#define NK 1024
#define ND 768
#define NKP 102
#define NBT (NB*NT)
#define INV_SQRT_D 0.03608439182435161f
#define NEG_INF (-3.402823466e38f)

// ---------------- device scratch (no allocations allowed) ----------------
__device__ __align__(16) static float g_emission[NBT * NK];     // 8 MB
__device__ __align__(16) static float g_transition[NK * NK];    // 4 MB (symmetric)
__device__ __align__(16) static float g_alpha_sum[2][NB * NK];
__device__ __align__(16) static float g_alpha_vit[2][NB * NK];
__device__ static unsigned short g_bp[(NT - 1) * NB * NK];      // backpointers
__device__ __align__(16) static float g_emtop[NBT * NKP];
__device__ __align__(16) static int   g_topidx[NBT * NKP];
__device__ __align__(16) static float g_appx[2][NB * NKP];
__device__ static float g_rowlse[NBT];
__device__ static float g_maxprob[NBT];
__device__ static float g_emy[NBT];
__device__ static int   g_smpred[NBT];
__device__ static float g_logZ[NB];
__device__ static float g_logZa[NB];
__device__ static int   g_crf[NBT];

// ---------------- GEMM: C[M,N] = scale * A[.,768] * B[.,768]^T ----------------
__device__ __forceinline__ void gemm_body(const float* __restrict__ A,
                                          const float* __restrict__ B,
                                          float* __restrict__ C,
                                          int N, float scale)
{
    __shared__ __align__(16) float As[16][64];
    __shared__ __align__(16) float Bs[16][64];
    int tid = threadIdx.x;
    int tx = tid & 15, ty = tid >> 4;
    int m0 = blockIdx.y * 64, n0 = blockIdx.x * 64;
    int lr = tid >> 2;            // 0..63
    int lc = (tid & 3) << 2;      // 0,4,8,12
    float acc[4][4];
#pragma unroll
    for (int i = 0; i < 4; i++)
#pragma unroll
        for (int j = 0; j < 4; j++) acc[i][j] = 0.f;

    for (int d0 = 0; d0 < ND; d0 += 16) {
        float4 a4 = *(const float4*)(A + (size_t)(m0 + lr) * ND + d0 + lc);
        float4 b4 = *(const float4*)(B + (size_t)(n0 + lr) * ND + d0 + lc);
        As[lc + 0][lr] = a4.x; As[lc + 1][lr] = a4.y; As[lc + 2][lr] = a4.z; As[lc + 3][lr] = a4.w;
        Bs[lc + 0][lr] = b4.x; Bs[lc + 1][lr] = b4.y; Bs[lc + 2][lr] = b4.z; Bs[lc + 3][lr] = b4.w;
        __syncthreads();
#pragma unroll
        for (int kk = 0; kk < 16; kk++) {
            float4 av = *(const float4*)(&As[kk][ty * 4]);
            float4 bv = *(const float4*)(&Bs[kk][tx * 4]);
            acc[0][0] += av.x * bv.x; acc[0][1] += av.x * bv.y; acc[0][2] += av.x * bv.z; acc[0][3] += av.x * bv.w;
            acc[1][0] += av.y * bv.x; acc[1][1] += av.y * bv.y; acc[1][2] += av.y * bv.z; acc[1][3] += av.y * bv.w;
            acc[2][0] += av.z * bv.x; acc[2][1] += av.z * bv.y; acc[2][2] += av.z * bv.z; acc[2][3] += av.z * bv.w;
            acc[3][0] += av.w * bv.x; acc[3][1] += av.w * bv.y; acc[3][2] += av.w * bv.z; acc[3][3] += av.w * bv.w;
        }
        __syncthreads();
    }
#pragma unroll
    for (int i = 0; i < 4; i++) {
        float4 o;
        o.x = acc[i][0] * scale; o.y = acc[i][1] * scale;
        o.z = acc[i][2] * scale; o.w = acc[i][3] * scale;
        *(float4*)(C + (size_t)(m0 + ty * 4 + i) * N + n0 + tx * 4) = o;
    }
}

__global__ __launch_bounds__(256) void k_gemm_em(const float* __restrict__ x,
                                                 const float* __restrict__ S)
{ gemm_body(x, S, g_emission, NK, INV_SQRT_D); }

__global__ __launch_bounds__(256) void k_gemm_tr(const float* __restrict__ S)
{ gemm_body(S, S, g_transition, NK, INV_SQRT_D); }

// ---------------- top-k (bitonic sort; slot order is irrelevant downstream) ----------------
__global__ __launch_bounds__(512) void topk_kernel(const int* __restrict__ y_lens)
{
    int row = blockIdx.x;
    int b = row >> 7, t = row & 127;
    if (t >= y_lens[b]) return;
    __shared__ float sv[NK];
    __shared__ int   si[NK];
    int tid = threadIdx.x;
    const float* em = g_emission + (size_t)row * NK;
    sv[tid] = em[tid];             si[tid] = tid;
    sv[tid + 512] = em[tid + 512]; si[tid + 512] = tid + 512;
    __syncthreads();
    for (int k = 2; k <= NK; k <<= 1) {
        for (int j = k >> 1; j > 0; j >>= 1) {
#pragma unroll 1
            for (int base = 0; base < NK; base += 512) {
                int i = base + tid;
                int ixj = i ^ j;
                if (ixj > i) {
                    bool up = ((i & k) == 0);
                    float a = sv[i], c = sv[ixj];
                    if ((a > c) == up) {
                        sv[i] = c; sv[ixj] = a;
                        int tmp = si[i]; si[i] = si[ixj]; si[ixj] = tmp;
                    }
                }
            }
            __syncthreads();
        }
    }
    if (tid < NKP) {
        g_emtop[(size_t)row * NKP + tid]  = sv[NK - NKP + tid];
        g_topidx[(size_t)row * NKP + tid] = si[NK - NKP + tid];
    }
}

// ---------------- per-row: lse, argmax(first-idx), max softmax prob, em_y ----------------
__global__ __launch_bounds__(256) void rowstats_kernel(const int* __restrict__ y)
{
    int row = blockIdx.x * 8 + (threadIdx.x >> 5);
    int lane = threadIdx.x & 31;
    const float* em = g_emission + (size_t)row * NK;
    float m = NEG_INF; int mi = 0;
    for (int i = lane; i < NK; i += 32) {
        float v = em[i];
        if (v > m) { m = v; mi = i; }
    }
#pragma unroll
    for (int off = 16; off; off >>= 1) {
        float om = __shfl_xor_sync(0xffffffffu, m, off);
        int   oi = __shfl_xor_sync(0xffffffffu, mi, off);
        if (om > m || (om == m && oi < mi)) { m = om; mi = oi; }
    }
    float s = 0.f;
    for (int i = lane; i < NK; i += 32) s += expf(em[i] - m);
#pragma unroll
    for (int off = 16; off; off >>= 1) s += __shfl_xor_sync(0xffffffffu, s, off);
    if (lane == 0) {
        float lse = m + logf(s);
        g_rowlse[row]  = lse;
        g_smpred[row]  = mi;
        g_maxprob[row] = expf(m - lse);
        g_emy[row]     = em[y[row]];
    }
}

// ---------------- persistent recursion kernel ----------------
// Clusters 0..15 (8 CTAs each): exact forward (linearized-exp GEMV) + Viterbi.
// CTAs 128..143 (clusters 16,17; no cluster.sync used): approx forward per batch.
__global__ __cluster_dims__(8, 1, 1) __launch_bounds__(256)
void persist_kernel(const int* __restrict__ y_lens)
{
    int cta = blockIdx.x;
    int tid = threadIdx.x;

    if (cta < 128) {
        int b = cta >> 3, part = cta & 7;
        int len = y_lens[b];
        int jbase0 = part * 128;

        __shared__ __align__(16) float shW[NK];
        __shared__ __align__(16) float shV[NK];
        __shared__ float redE[8];
        __shared__ float shE;

        // t = 0 init for my j-range
        if (tid < 128) {
            float e = g_emission[(size_t)(b << 7) * NK + jbase0 + tid];
            g_alpha_sum[0][(b << 10) + jbase0 + tid] = e;
            g_alpha_vit[0][(b << 10) + jbase0 + tid] = e;
        }

        for (int t = 1; t < len; t++) {
            // cluster barrier: release/acquire; also acts as intra-CTA barrier.
            asm volatile("barrier.cluster.arrive.aligned;" ::: "memory");
            asm volatile("barrier.cluster.wait.aligned;"   ::: "memory");

            const float* prevS = g_alpha_sum[(t - 1) & 1] + (b << 10);
            const float* prevV = g_alpha_vit[(t - 1) & 1] + (b << 10);
            float* curS = g_alpha_sum[t & 1] + (b << 10);
            float* curV = g_alpha_vit[t & 1] + (b << 10);

            float shift = __ldcv(prevS);   // any per-batch shift works; L1-bypass
            // load prev alphas (L1-bypass: peer-CTA written), build w = exp(aS - shift)
            float4 s4 = __ldcv((const float4*)(prevS + tid * 4));
            float4 v4 = __ldcv((const float4*)(prevV + tid * 4));
            float w0 = __expf(s4.x - shift), w1 = __expf(s4.y - shift);
            float w2 = __expf(s4.z - shift), w3 = __expf(s4.w - shift);
            ((float4*)shW)[tid] = make_float4(w0, w1, w2, w3);
            ((float4*)shV)[tid] = v4;
            float psum = (w0 + w1) + (w2 + w3);
#pragma unroll
            for (int off = 16; off; off >>= 1)
                psum += __shfl_xor_sync(0xffffffffu, psum, off);
            if ((tid & 31) == 0) redE[tid >> 5] = psum;
            __syncthreads();
            if (tid == 0) {
                float e = (((redE[0] + redE[1]) + (redE[2] + redE[3]))
                         + ((redE[4] + redE[5]) + (redE[6] + redE[7])));
                shE = e;
            }
            __syncthreads();
            float E = shE;

            int w = tid >> 5, lane = tid & 31;
            int jbase = jbase0 + w * 16;
            float acc[16], vmax[16];
            int vidx[16];
#pragma unroll
            for (int jj = 0; jj < 16; jj++) { acc[jj] = 0.f; vmax[jj] = NEG_INF; vidx[jj] = 0; }
#pragma unroll 1
            for (int i0 = 0; i0 < NK; i0 += 128) {
                int i = i0 + (lane << 2);
                float4 w4  = *(const float4*)(shW + i);
                float4 av4 = *(const float4*)(shV + i);
#pragma unroll
                for (int jj = 0; jj < 16; jj++) {
                    // T symmetric bitwise: row (jbase+jj) contiguous in i (L1-cached)
                    float4 t4 = __ldg((const float4*)(g_transition + (size_t)(jbase + jj) * NK + i));
                    acc[jj] = fmaf(w4.x, t4.x, acc[jj]);
                    acc[jj] = fmaf(w4.y, t4.y, acc[jj]);
                    acc[jj] = fmaf(w4.z, t4.z, acc[jj]);
                    acc[jj] = fmaf(w4.w, t4.w, acc[jj]);
                    float v0 = av4.x + t4.x; if (v0 > vmax[jj]) { vmax[jj] = v0; vidx[jj] = i; }
                    float v1 = av4.y + t4.y; if (v1 > vmax[jj]) { vmax[jj] = v1; vidx[jj] = i + 1; }
                    float v2 = av4.z + t4.z; if (v2 > vmax[jj]) { vmax[jj] = v2; vidx[jj] = i + 2; }
                    float v3 = av4.w + t4.w; if (v3 > vmax[jj]) { vmax[jj] = v3; vidx[jj] = i + 3; }
                }
            }
            const float* emrow = g_emission + (size_t)((b << 7) + t) * NK;
#pragma unroll
            for (int jj = 0; jj < 16; jj++) {
                float a = acc[jj], m = vmax[jj];
                int id = vidx[jj];
#pragma unroll
                for (int off = 16; off; off >>= 1) {
                    a += __shfl_xor_sync(0xffffffffu, a, off);
                    float om = __shfl_xor_sync(0xffffffffu, m, off);
                    int   oi = __shfl_xor_sync(0xffffffffu, id, off);
                    if (om > m || (om == m && oi < id)) { m = om; id = oi; }
                }
                if (lane == 0) {
                    int j = jbase + jj;
                    float em = emrow[j];
                    curS[j] = shift + __logf(E + a) + em;   // sum_i exp(aS_i+T_ij) = E + sum_i w_i T_ij
                    curV[j] = m + em;
                    g_bp[(size_t)(t - 1) * (NB * NK) + (b << 10) + j] = (unsigned short)id;
                }
            }
        }
    } else {
        // -------- approx forward, one CTA per batch --------
        int ba = cta - 128;
        int len = y_lens[ba];
        __shared__ float pA[NKP];
        __shared__ int   pI[NKP];
        __shared__ float pW[NKP];
        __shared__ float sEa;

        if (tid < NKP)
            g_appx[0][ba * NKP + tid] = g_emtop[(size_t)(ba << 7) * NKP + tid];
        __syncthreads();

        for (int t = 1; t < len; t++) {
            int row = (ba << 7) + t, prow = row - 1;
            if (tid < NKP) {
                pA[tid] = g_appx[(t - 1) & 1][ba * NKP + tid];
                pI[tid] = g_topidx[(size_t)prow * NKP + tid];
            }
            __syncthreads();
            float shift = pA[0];
            if (tid < NKP) pW[tid] = __expf(pA[tid] - shift);
            __syncthreads();
            if (tid == 0) {
                float e = 0.f;
                for (int i = 0; i < NKP; i++) e += pW[i];
                sEa = e;
            }
            __syncthreads();
            if (tid < NKP) {
                int jc = g_topidx[(size_t)row * NKP + tid];
                const float* Tc = g_transition + jc;
                float s0 = 0.f, s1 = 0.f, s2 = 0.f, s3 = 0.f;
#pragma unroll 2
                for (int i = 0; i + 4 <= NKP; i += 4) {
                    float t0 = __ldg(Tc + (size_t)pI[i + 0] * NK);
                    float t1 = __ldg(Tc + (size_t)pI[i + 1] * NK);
                    float t2 = __ldg(Tc + (size_t)pI[i + 2] * NK);
                    float t3 = __ldg(Tc + (size_t)pI[i + 3] * NK);
                    s0 = fmaf(pW[i + 0], t0, s0);
                    s1 = fmaf(pW[i + 1], t1, s1);
                    s2 = fmaf(pW[i + 2], t2, s2);
                    s3 = fmaf(pW[i + 3], t3, s3);
                }
                // remainder (NKP = 102 = 4*25 + 2)
                s0 = fmaf(pW[100], __ldg(Tc + (size_t)pI[100] * NK), s0);
                s1 = fmaf(pW[101], __ldg(Tc + (size_t)pI[101] * NK), s1);
                float s = ((s0 + s1) + (s2 + s3)) + sEa;
                g_appx[t & 1][ba * NKP + tid] =
                    shift + __logf(s) + g_emtop[(size_t)row * NKP + tid];
            }
            __syncthreads();
        }
    }
}

// ---------------- last-state / log_Z / backtrace ----------------
__global__ __launch_bounds__(512) void trace_kernel(const int* __restrict__ y_lens,
                                                    float* __restrict__ out)
{
    __shared__ int sh_last[NB];
    int tid = threadIdx.x;
    int b = tid >> 5, lane = tid & 31;
    int len = y_lens[b];
    int par = (len - 1) & 1;
    {   // argmax of viterbi a_last (first index on ties)
        const float* av = g_alpha_vit[par] + (b << 10);
        float m = NEG_INF; int mi = 0;
        for (int j = lane; j < NK; j += 32) {
            float v = av[j];
            if (v > m) { m = v; mi = j; }
        }
#pragma unroll
        for (int off = 16; off; off >>= 1) {
            float om = __shfl_xor_sync(0xffffffffu, m, off);
            int   oi = __shfl_xor_sync(0xffffffffu, mi, off);
            if (om > m || (om == m && oi < mi)) { m = om; mi = oi; }
        }
        if (lane == 0) sh_last[b] = mi;
    }
    {   // log_Z (exact)
        const float* as = g_alpha_sum[par] + (b << 10);
        float m = NEG_INF;
        for (int j = lane; j < NK; j += 32) m = fmaxf(m, as[j]);
#pragma unroll
        for (int off = 16; off; off >>= 1) m = fmaxf(m, __shfl_xor_sync(0xffffffffu, m, off));
        float s = 0.f;
        for (int j = lane; j < NK; j += 32) s += expf(as[j] - m);
#pragma unroll
        for (int off = 16; off; off >>= 1) s += __shfl_xor_sync(0xffffffffu, s, off);
        if (lane == 0) g_logZ[b] = m + logf(s);
    }
    {   // log_Z approx
        const float* aa = g_appx[par] + b * NKP;
        float m = NEG_INF;
        for (int j = lane; j < NKP; j += 32) m = fmaxf(m, aa[j]);
#pragma unroll
        for (int off = 16; off; off >>= 1) m = fmaxf(m, __shfl_xor_sync(0xffffffffu, m, off));
        float s = 0.f;
        for (int j = lane; j < NKP; j += 32) s += expf(aa[j] - m);
#pragma unroll
        for (int off = 16; off; off >>= 1) s += __shfl_xor_sync(0xffffffffu, s, off);
        if (lane == 0) g_logZa[b] = m + logf(s);
    }
    __syncthreads();
    if (tid < NB) {
        int bb = tid;
        int ll = y_lens[bb];
        int last = sh_last[bb];
        int s = 0;
        for (int t = NT - 1; t >= 0; --t) {
            if (t == ll - 1)      s = last;
            else if (t < ll - 1)  s = (int)g_bp[(size_t)t * (NB * NK) + (bb << 10) + s];
            else                  s = 0;
            g_crf[(bb << 7) + t] = s;
            out[1 + (bb << 7) + t] = (float)s;
        }
    }
}

// ---------------- final scalar reductions ----------------
__global__ __launch_bounds__(512) void final_kernel(const int* __restrict__ y,
                                                    const int* __restrict__ y_lens,
                                                    float* __restrict__ out)
{
    __shared__ float sh_emy[NB], sh_lse[NB], sh_tr[NB], sh_mp[NB];
    __shared__ float sh_sup[NB], sh_eqc[NB], sh_pc[NB], sh_ovc[NB];
    __shared__ float sh_eqs[NB], sh_ps[NB], sh_ovs[NB];
    int tid = threadIdx.x;
    int b = tid >> 5, lane = tid & 31;
    int len = y_lens[b];
    float emy = 0.f, lse = 0.f, tr = 0.f, mp = 0.f;
    float sup = 0.f, eqc = 0.f, pc = 0.f, ovc = 0.f, eqs = 0.f, ps = 0.f, ovs = 0.f;
    for (int t = lane; t < NT; t += 32) {
        int row = (b << 7) + t;
        if (t < len) {
            emy += g_emy[row];
            lse += g_rowlse[row];
            mp  += g_maxprob[row];
            int yv = y[row];
            int cp = g_crf[row];
            int sp = g_smpred[row];
            sup += (yv > 0) ? 1.f : 0.f;
            eqc += (cp == yv) ? 1.f : 0.f;
            pc  += (cp > 0) ? 1.f : 0.f;
            ovc += (cp > 0 && yv > 0) ? 1.f : 0.f;
            eqs += (sp == yv) ? 1.f : 0.f;
            ps  += (sp > 0) ? 1.f : 0.f;
            ovs += (sp > 0 && yv > 0) ? 1.f : 0.f;
        }
        if (t < NT - 1 && t < len - 1)
            tr += g_transition[(size_t)y[(b << 7) + t] * NK + y[(b << 7) + t + 1]];
    }
#pragma unroll
    for (int off = 16; off; off >>= 1) {
        emy += __shfl_xor_sync(0xffffffffu, emy, off);
        lse += __shfl_xor_sync(0xffffffffu, lse, off);
        tr  += __shfl_xor_sync(0xffffffffu, tr,  off);
        mp  += __shfl_xor_sync(0xffffffffu, mp,  off);
        sup += __shfl_xor_sync(0xffffffffu, sup, off);
        eqc += __shfl_xor_sync(0xffffffffu, eqc, off);
        pc  += __shfl_xor_sync(0xffffffffu, pc,  off);
        ovc += __shfl_xor_sync(0xffffffffu, ovc, off);
        eqs += __shfl_xor_sync(0xffffffffu, eqs, off);
        ps  += __shfl_xor_sync(0xffffffffu, ps,  off);
        ovs += __shfl_xor_sync(0xffffffffu, ovs, off);
    }
    if (lane == 0) {
        sh_emy[b] = emy; sh_lse[b] = lse; sh_tr[b] = tr; sh_mp[b] = mp;
        sh_sup[b] = sup; sh_eqc[b] = eqc; sh_pc[b] = pc; sh_ovc[b] = ovc;
        sh_eqs[b] = eqs; sh_ps[b] = ps; sh_ovs[b] = ovs;
    }
    __syncthreads();
    if (tid == 0) {
        float totlen = 0.f;
        float sZ = 0.f, sZa = 0.f, sExact = 0.f, sApprox = 0.f, sLocal = 0.f, sMp = 0.f;
        float tsup = 0.f, teqc = 0.f, tpc = 0.f, tovc = 0.f, teqs = 0.f, tps = 0.f, tovs = 0.f;
        for (int bb = 0; bb < NB; bb++) {
            totlen += (float)y_lens[bb];
            float logpot = sh_emy[bb] + sh_tr[bb];
            sZ  += g_logZ[bb];
            sZa += g_logZa[bb];
            sExact  += logpot - g_logZ[bb];
            sApprox += logpot - g_logZa[bb];
            sLocal  += sh_emy[bb] - sh_lse[bb];
            sMp     += sh_mp[bb];
            tsup += sh_sup[bb]; teqc += sh_eqc[bb]; tpc += sh_pc[bb]; tovc += sh_ovc[bb];
            teqs += sh_eqs[bb]; tps += sh_ps[bb]; tovs += sh_ovs[bb];
        }
        float exactv  = -sExact / (float)NB;
        float approxv = -sApprox / (float)NB;
        float localv  = sLocal / totlen;
        float maxpv   = sMp / totlen;
        float loss    = approxv + 0.1f * localv;

        float crf_acc = teqc / totlen;
        float crf_prec = (tpc > 0.f) ? tovc / fmaxf(tpc, 1.f) : 0.f;
        float crf_recl = tovc / fmaxf(tsup, 1.f);
        float crf_f1 = (crf_prec > 0.f)
            ? 2.f * crf_prec * crf_recl / fmaxf(crf_prec + crf_recl, 1e-12f) : 0.f;

        float sm_acc = teqs / totlen;
        float sm_prec = (tps > 0.f) ? tovs / fmaxf(tps, 1.f) : 0.f;
        float sm_recl = tovs / fmaxf(tsup, 1.f);
        float sm_f1 = (sm_prec > 0.f)
            ? 2.f * sm_prec * sm_recl / fmaxf(sm_prec + sm_recl, 1e-12f) : 0.f;

        out[0]    = loss;
        out[2049] = sZ / (float)NB;
        out[2050] = sZa / (float)NB;
        out[2051] = exactv;
        out[2052] = localv;
        out[2053] = maxpv;
        out[2054] = crf_acc;
        out[2055] = crf_f1;
        out[2056] = sm_acc;
        out[2057] = sm_f1;
    }
}

// ---------------- launch ----------------
extern "C" void kernel_launch(void* const* d_in, const int* in_sizes, int n_in,
                              void* d_out, int out_size) {
    const float* x_emb = (const float*)d_in[0];
    const float* S     = (const float*)d_in[1];
    const int*   y     = (const int*)d_in[2];
    const int*   lens  = (const int*)d_in[3];
    float* out = (float*)d_out;

    k_gemm_tr<<<dim3(16, 16), 256>>>(S);
    k_gemm_em<<<dim3(16, 32), 256>>>(x_emb, S);
    topk_kernel<<<NBT, 512>>>(lens);
    rowstats_kernel<<<256, 256>>>(y);
    persist_kernel<<<144, 256>>>(lens);
    trace_kernel<<<1, 512>>>(lens, out);
    final_kernel<<<1, 512>>>(y, lens, out);
}